// round 1
// baseline (speedup 1.0000x reference)
#include <cuda_runtime.h>

// EquivariantLayerNorm, specialized to IRREPS=[(256,0),(128,1),(64,2),(32,3)]
//   dim = 1184, f4-per-row = 296
//   group f4 ranges: g0 [0,64) g1 [64,160) g2 [160,240) g3 [240,296)
//   group element counts: 256, 384, 320, 224
//   scalar columns == group 0 columns (single scalar group)
// Math per row:
//   smean = mean(x[g0]);  var0 = mean(x[g0]^2) - smean^2;  var_g = mean(x[g]^2), g>=1
//   out = (x - smean*[g==0]) * rsqrt(var_g + eps) * weight[irrep_idx[c]] + bias_full[c]

#define DIM   1184
#define NF4   296
#define EPSV  1e-5f

__device__ __align__(16) float d_colW[DIM];   // weight[irrep_idx[c]]
__device__ __align__(16) float d_colB[DIM];   // bias scattered to full dim

__global__ void setup_kernel(const float* __restrict__ weight,
                             const float* __restrict__ bias,
                             const int*   __restrict__ irrep_idx,
                             const int*   __restrict__ scalar_indices,
                             int dim, int sdim) {
    int t = threadIdx.x;
    for (int c = t; c < dim; c += blockDim.x) {
        d_colW[c] = weight[irrep_idx[c]];
        d_colB[c] = 0.f;
    }
    __syncthreads();
    for (int i = t; i < sdim; i += blockDim.x) {
        d_colB[scalar_indices[i]] = bias[i];
    }
}

__global__ __launch_bounds__(256) void eln_kernel(const float* __restrict__ x,
                                                  float* __restrict__ out) {
    const int row = blockIdx.x;
    const int t   = threadIdx.x;
    const float4* __restrict__ xr   = (const float4*)(x   + (size_t)row * DIM);
    float4*       __restrict__ orow = (float4*)      (out + (size_t)row * DIM);

    // Load: thread t owns f4 index t; threads [0,40) additionally own t+256 (group 3).
    float4 v0 = xr[t];
    const bool has1 = (t < NF4 - 256);        // t < 40
    float4 v1 = make_float4(0.f, 0.f, 0.f, 0.f);
    if (has1) v1 = xr[t + 256];

    float q0 = v0.x*v0.x + v0.y*v0.y + v0.z*v0.z + v0.w*v0.w;
    float q1 = v1.x*v1.x + v1.y*v1.y + v1.z*v1.z + v1.w*v1.w;

    float s1 = 0.f, s2_0 = 0.f, s2_1 = 0.f, s2_2 = 0.f, s2_3 = 0.f;
    if (t < 64) {                 // group 0 (scalar)
        s2_0 = q0;
        s1   = v0.x + v0.y + v0.z + v0.w;
    } else if (t < 160) {         // group 1
        s2_1 = q0;
    } else if (t < 240) {         // group 2
        s2_2 = q0;
    } else {                      // group 3
        s2_3 = q0;
    }
    s2_3 += q1;                   // second element is always group 3

    // Warp reduction of 5 partials
    #pragma unroll
    for (int off = 16; off; off >>= 1) {
        s1   += __shfl_xor_sync(0xffffffffu, s1,   off);
        s2_0 += __shfl_xor_sync(0xffffffffu, s2_0, off);
        s2_1 += __shfl_xor_sync(0xffffffffu, s2_1, off);
        s2_2 += __shfl_xor_sync(0xffffffffu, s2_2, off);
        s2_3 += __shfl_xor_sync(0xffffffffu, s2_3, off);
    }

    __shared__ float red[8][5];
    __shared__ float bc[5];       // {smean, rn0, rn1, rn2, rn3}
    const int warp = t >> 5, lane = t & 31;
    if (lane == 0) {
        red[warp][0] = s1;
        red[warp][1] = s2_0;
        red[warp][2] = s2_1;
        red[warp][3] = s2_2;
        red[warp][4] = s2_3;
    }
    __syncthreads();
    if (t == 0) {
        float a0 = 0.f, a1 = 0.f, a2 = 0.f, a3 = 0.f, a4 = 0.f;
        #pragma unroll
        for (int w = 0; w < 8; w++) {
            a0 += red[w][0]; a1 += red[w][1]; a2 += red[w][2];
            a3 += red[w][3]; a4 += red[w][4];
        }
        float smean = a0 * (1.f / 256.f);
        bc[0] = smean;
        bc[1] = rsqrtf(a1 * (1.f / 256.f) - smean * smean + EPSV);
        bc[2] = rsqrtf(a2 * (1.f / 384.f) + EPSV);
        bc[3] = rsqrtf(a3 * (1.f / 320.f) + EPSV);
        bc[4] = rsqrtf(a4 * (1.f / 224.f) + EPSV);
    }
    __syncthreads();

    const float smean = bc[0];
    float rn, sub0 = 0.f;
    if (t < 64)       { rn = bc[1]; sub0 = smean; }
    else if (t < 160) { rn = bc[2]; }
    else if (t < 240) { rn = bc[3]; }
    else              { rn = bc[4]; }

    const float4* __restrict__ w4p = (const float4*)d_colW;
    const float4* __restrict__ b4p = (const float4*)d_colB;

    {
        float4 w = w4p[t], b = b4p[t], o;
        o.x = (v0.x - sub0) * rn * w.x + b.x;
        o.y = (v0.y - sub0) * rn * w.y + b.y;
        o.z = (v0.z - sub0) * rn * w.z + b.z;
        o.w = (v0.w - sub0) * rn * w.w + b.w;
        orow[t] = o;
    }
    if (has1) {
        const float rn3 = bc[4];
        float4 w = w4p[t + 256], b = b4p[t + 256], o;
        o.x = v1.x * rn3 * w.x + b.x;
        o.y = v1.y * rn3 * w.y + b.y;
        o.z = v1.z * rn3 * w.z + b.z;
        o.w = v1.w * rn3 * w.w + b.w;
        orow[t + 256] = o;
    }
}

extern "C" void kernel_launch(void* const* d_in, const int* in_sizes, int n_in,
                              void* d_out, int out_size) {
    const float* x              = (const float*)d_in[0];
    const float* weight         = (const float*)d_in[1];
    const float* bias           = (const float*)d_in[2];
    const int*   irrep_idx      = (const int*)  d_in[4];
    const int*   scalar_indices = (const int*)  d_in[5];

    const int dim  = in_sizes[3];          // group_idx length = 1184
    const int sdim = in_sizes[5];          // scalar_indices length = 256
    const int n    = in_sizes[0] / dim;    // 65536 rows

    setup_kernel<<<1, 256>>>(weight, bias, irrep_idx, scalar_indices, dim, sdim);
    eln_kernel<<<n, 256>>>(x, (float*)d_out);
}